// round 15
// baseline (speedup 1.0000x reference)
#include <cuda_runtime.h>
#include <cuda_fp16.h>
#include <math.h>

// ---------------- problem constants (fixed by setup_inputs) ----------------
#define N_NODES 50000
#define N_EDGES 800000
#define ET      (N_EDGES + N_NODES)   // edges + self loops = 850000
#define H       2
#define C0      128
#define C1      100
#define F0      17
#define HC0     (H * C0)              // 256
#define HC1     (H * C1)              // 200
#define NEG_SLOPE 0.2f
#define EPS_DEN   1e-16f
#define PAD     96                    // bucket capacity; P(Poisson(17) > 96) ~ 1e-44

// ---------------- scratch (static device globals; no allocation) -----------
__device__ __align__(16) float  g_agg0[(long long)N_NODES * HC0];  // x1 after gather0
__device__ __align__(16) __half g_h0h[(long long)N_NODES * HC0];   // fp16 features L0
__device__ __align__(16) __half g_h1h[(long long)N_NODES * HC1];   // fp16 features L1
__device__ __align__(16) float  g_asrc[N_NODES * H];
__device__ __align__(16) float  g_adst[N_NODES * H];
__device__ __align__(16) int    g_pos[N_NODES];   // zero-init at load; re-zeroed by gather1
__device__ __align__(16) int    g_adjpad[(long long)N_NODES * PAD];

// ---------------- helpers --------------------------------------------------
__device__ __forceinline__ int clampN(int v) {
    return v < 0 ? 0 : (v >= N_NODES ? N_NODES - 1 : v);
}
__device__ __forceinline__ float lrelu(float v) {
    return (v >= 0.0f) ? v : NEG_SLOPE * v;
}
// packed fp32x2 FMA (Blackwell; PTX-only)
__device__ __forceinline__ void fma2(unsigned long long& acc,
                                     unsigned long long a,
                                     unsigned long long b) {
    asm("fma.rn.f32x2 %0, %1, %2, %0;" : "+l"(acc) : "l"(a), "l"(b));
}

// ---------------- decode edges + self loops into padded dst buckets --------
// Per-block dtype detection: for int64 data every odd 32-bit word of the
// first 64 words is 0; impossible for 32 random int32 node ids.
__global__ void k_fill(const int* __restrict__ e32) {
    __shared__ int sh_is64;
    if (threadIdx.x < 32) {
        int w = e32[2 * threadIdx.x + 1];
        unsigned b = __ballot_sync(0xffffffffu, w != 0);
        if (threadIdx.x == 0) sh_is64 = (b == 0) ? 1 : 0;
    }
    __syncthreads();
    const int is64 = sh_is64;

    int i = blockIdx.x * blockDim.x + threadIdx.x;
    if (i >= ET) return;
    int s, d;
    if (i < N_EDGES) {
        if (is64) {
            s = e32[2 * i];
            d = e32[2 * N_EDGES + 2 * i];
        } else {
            s = e32[i];
            d = e32[N_EDGES + i];
        }
        s = clampN(s); d = clampN(d);
    } else {
        s = d = i - N_EDGES;
    }
    int slot = atomicAdd(&g_pos[d], 1);
    if (slot < PAD) g_adjpad[d * PAD + slot] = s;
}

// ---------------- GEMM layer 0 + fused alpha0 ------------------------------
__global__ void k_gemm0a(const float* __restrict__ x, const float* __restrict__ W,
                         const float* __restrict__ asrc, const float* __restrict__ adst) {
    __shared__ float xs[8][F0];
    __shared__ float sred[8][8][2];   // [warp][node][src/dst]
    const int n0 = blockIdx.x * 8;
    const int t  = threadIdx.x;  // column 0..255
    for (int i = t; i < 8 * F0; i += 256) {
        int n = i / F0, k = i % F0, nn = n0 + n;
        xs[n][k] = (nn < N_NODES) ? x[(long long)nn * F0 + k] : 0.0f;
    }
    __syncthreads();
    float acc[8];
#pragma unroll
    for (int n = 0; n < 8; n++) acc[n] = 0.0f;
#pragma unroll
    for (int k = 0; k < F0; k++) {
        float w = W[k * HC0 + t];
#pragma unroll
        for (int n = 0; n < 8; n++) acc[n] += xs[n][k] * w;
    }
#pragma unroll
    for (int n = 0; n < 8; n++) {
        int nn = n0 + n;
        if (nn < N_NODES) g_h0h[(unsigned)nn * HC0 + t] = __float2half_rn(acc[n]);
    }
    // fused alpha: per-column contribution, warp-reduce, stage per warp
    const int warp = t >> 5, lane = t & 31;
    const float as_t = asrc[t];
    const float ad_t = adst[t];
#pragma unroll
    for (int n = 0; n < 8; n++) {
        float vs = acc[n] * as_t;
        float vd = acc[n] * ad_t;
#pragma unroll
        for (int o = 16; o; o >>= 1) {
            vs += __shfl_xor_sync(0xffffffffu, vs, o);
            vd += __shfl_xor_sync(0xffffffffu, vd, o);
        }
        if (lane == 0) {
            sred[warp][n][0] = vs;
            sred[warp][n][1] = vd;
        }
    }
    __syncthreads();
    if (t < 32) {
        int n = t >> 2, hd = (t >> 1) & 1, q = t & 1;
        float s = 0.0f;
#pragma unroll
        for (int w = 0; w < 4; w++) s += sred[hd * 4 + w][n][q];
        int nn = n0 + n;
        if (nn < N_NODES) {
            if (q == 0) g_asrc[nn * H + hd] = s;
            else        g_adst[nn * H + hd] = s;
        }
    }
}

// ---------------- GEMM layer 1: h1 = x1 @ W1 ([N,256] x [256,200]) ---------
__global__ void k_gemm1(const float* __restrict__ W) {
    __shared__ __align__(16) float xs[HC0][36];
    const int n0 = blockIdx.x * 32;
    const int t  = threadIdx.x;
    for (int i = t; i < 32 * HC0; i += 256) {
        int n = i >> 8, k = i & 255, nn = n0 + n;
        xs[k][n] = (nn < N_NODES) ? g_agg0[(unsigned)nn * HC0 + k] : 0.0f;
    }
    __syncthreads();
    if (t < HC1) {
        unsigned long long acc2[16];
#pragma unroll
        for (int j = 0; j < 16; j++) acc2[j] = 0ull;
#pragma unroll 2
        for (int k = 0; k < HC0; k++) {
            float w = W[k * HC1 + t];
            unsigned long long w2;
            unsigned wu = __float_as_uint(w);
            asm("mov.b64 %0, {%1, %1};" : "=l"(w2) : "r"(wu));
#pragma unroll
            for (int j = 0; j < 8; j++) {
                ulonglong2 v = *(const ulonglong2*)&xs[k][4 * j];
                fma2(acc2[2 * j + 0], v.x, w2);
                fma2(acc2[2 * j + 1], v.y, w2);
            }
        }
#pragma unroll
        for (int j = 0; j < 16; j++) {
            unsigned lo, hi;
            asm("mov.b64 {%0, %1}, %2;" : "=r"(lo), "=r"(hi) : "l"(acc2[j]));
            int na = n0 + 2 * j, nb = na + 1;
            if (na < N_NODES) g_h1h[(unsigned)na * HC1 + t] = __float2half_rn(__uint_as_float(lo));
            if (nb < N_NODES) g_h1h[(unsigned)nb * HC1 + t] = __float2half_rn(__uint_as_float(hi));
        }
    }
}

// ---------------- attention logits layer 1 (fp16 h, warp per node) ---------
__global__ void k_alpha1(const float* __restrict__ asrc,
                         const float* __restrict__ adst) {
    constexpr int C  = C1;
    constexpr int HC = HC1;
    constexpr int NL = HC / 8;   // 25
    const __half* h = g_h1h;

    int n    = (blockIdx.x * blockDim.x + threadIdx.x) >> 5;
    int lane = threadIdx.x & 31;
    if (n >= N_NODES) return;
    const int  cbase = 8 * lane;
    float s0 = 0.f, s1 = 0.f, d0 = 0.f, d1 = 0.f;
    if (lane < NL) {
        uint4 v = *(const uint4*)(h + (unsigned)n * HC + cbase);
        const __half2* hv = (const __half2*)&v;
        float2 f0 = __half22float2(hv[0]);
        float2 f1 = __half22float2(hv[1]);
        float2 f2 = __half22float2(hv[2]);
        float2 f3 = __half22float2(hv[3]);
        float4 aA = *(const float4*)(asrc + cbase);
        float4 aB = *(const float4*)(asrc + cbase + 4);
        float4 dA = *(const float4*)(adst + cbase);
        float4 dB = *(const float4*)(adst + cbase + 4);
        float sA = f0.x * aA.x + f0.y * aA.y + f1.x * aA.z + f1.y * aA.w;
        float sB = f2.x * aB.x + f2.y * aB.y + f3.x * aB.z + f3.y * aB.w;
        float dAv = f0.x * dA.x + f0.y * dA.y + f1.x * dA.z + f1.y * dA.w;
        float dBv = f2.x * dB.x + f2.y * dB.y + f3.x * dB.z + f3.y * dB.w;
        if (cbase >= C)     { s1 += sA; d1 += dAv; } else { s0 += sA; d0 += dAv; }
        if (cbase + 4 >= C) { s1 += sB; d1 += dBv; } else { s0 += sB; d0 += dBv; }
    }
#pragma unroll
    for (int o = 16; o; o >>= 1) {
        s0 += __shfl_xor_sync(0xffffffffu, s0, o);
        s1 += __shfl_xor_sync(0xffffffffu, s1, o);
        d0 += __shfl_xor_sync(0xffffffffu, d0, o);
        d1 += __shfl_xor_sync(0xffffffffu, d1, o);
    }
    if (lane == 0) {
        g_asrc[n * H + 0] = s0;
        g_asrc[n * H + 1] = s1;
        g_adst[n * H + 0] = d0;
        g_adst[n * H + 1] = d1;
    }
}

// ---------------- gather aggregation: one warp per dst ---------------------
// LAYER 1 re-zeroes g_pos[d] after reading (replaces the init kernel for the
// next invocation; device globals start zeroed at module load).
template <int LAYER>
__global__ void k_gather(float* __restrict__ out_param,
                         const float* __restrict__ bias) {
    constexpr int C  = (LAYER == 0) ? C0  : C1;
    constexpr int HC = (LAYER == 0) ? HC0 : HC1;
    constexpr int NL = HC / 8;                  // load lanes: 32 (L0), 25 (L1)
    const __half* h = (LAYER == 0) ? g_h0h : g_h1h;
    float* out      = (LAYER == 0) ? g_agg0 : out_param;

    __shared__ __align__(16) float4 stage[8][32];   // [warp][edge-in-chunk]

    int d    = (blockIdx.x * blockDim.x + threadIdx.x) >> 5;
    int warp = threadIdx.x >> 5;
    int lane = threadIdx.x & 31;
    if (d >= N_NODES) return;

    const int  cbase = 8 * lane;
    const bool headA = (cbase >= C);
    const bool headB = (cbase + 4 >= C);

    const unsigned row0 = (unsigned)d * PAD;
    int deg = g_pos[d]; if (deg > PAD) deg = PAD;
    if (LAYER == 1 && lane == 0) g_pos[d] = 0;   // reset for next call
    float ad0 = g_adst[d * H + 0];
    float ad1 = g_adst[d * H + 1];

    float accA0 = 0.f, accA1 = 0.f, accA2 = 0.f, accA3 = 0.f;
    float accB0 = 0.f, accB1 = 0.f, accB2 = 0.f, accB3 = 0.f;
    float s0 = 0.0f, s1 = 0.0f;
    for (int j0 = 0; j0 < deg; j0 += 32) {
        int j = j0 + lane;
        int   sn = 0;
        float p0 = 0.0f, p1 = 0.0f;
        if (j < deg) {
            sn = g_adjpad[row0 + j];
            float2 av = *(const float2*)&g_asrc[sn * H];
            p0 = __expf(fminf(lrelu(av.x + ad0), 80.0f));
            p1 = __expf(fminf(lrelu(av.y + ad1), 80.0f));
        }
        s0 += p0;
        s1 += p1;
        stage[warp][lane] = make_float4(__int_as_float(sn), p0, p1, 0.0f);
        __syncwarp();
        int cnt = deg - j0; if (cnt > 32) cnt = 32;
#pragma unroll 4
        for (int k = 0; k < cnt; k++) {
            float4 e = stage[warp][k];           // LDS.128 broadcast
            if (lane < NL) {
                unsigned sk = (unsigned)__float_as_int(e.x);
                uint4 v = *(const uint4*)(h + sk * HC + cbase);
                const __half2* hv = (const __half2*)&v;
                float2 f0 = __half22float2(hv[0]);
                float2 f1 = __half22float2(hv[1]);
                float2 f2 = __half22float2(hv[2]);
                float2 f3 = __half22float2(hv[3]);
                float wA = headA ? e.z : e.y;
                float wB = headB ? e.z : e.y;
                accA0 += wA * f0.x; accA1 += wA * f0.y;
                accA2 += wA * f1.x; accA3 += wA * f1.y;
                accB0 += wB * f2.x; accB1 += wB * f2.y;
                accB2 += wB * f3.x; accB3 += wB * f3.y;
            }
        }
        __syncwarp();
    }
#pragma unroll
    for (int o = 16; o; o >>= 1) {
        s0 += __shfl_xor_sync(0xffffffffu, s0, o);
        s1 += __shfl_xor_sync(0xffffffffu, s1, o);
    }
    float inv0 = 1.0f / (s0 + EPS_DEN);
    float inv1 = 1.0f / (s1 + EPS_DEN);

    if (lane < NL) {
        float invA = headA ? inv1 : inv0;
        float invB = headB ? inv1 : inv0;
        float4 ba = *(const float4*)(bias + cbase);
        float4 bb = *(const float4*)(bias + cbase + 4);
        float4 ra, rb;
        ra.x = accA0 * invA + ba.x; ra.y = accA1 * invA + ba.y;
        ra.z = accA2 * invA + ba.z; ra.w = accA3 * invA + ba.w;
        rb.x = accB0 * invB + bb.x; rb.y = accB1 * invB + bb.y;
        rb.z = accB2 * invB + bb.z; rb.w = accB3 * invB + bb.w;
        if (LAYER == 0) {  // ELU between layers
            ra.x = (ra.x > 0.f) ? ra.x : expm1f(ra.x);
            ra.y = (ra.y > 0.f) ? ra.y : expm1f(ra.y);
            ra.z = (ra.z > 0.f) ? ra.z : expm1f(ra.z);
            ra.w = (ra.w > 0.f) ? ra.w : expm1f(ra.w);
            rb.x = (rb.x > 0.f) ? rb.x : expm1f(rb.x);
            rb.y = (rb.y > 0.f) ? rb.y : expm1f(rb.y);
            rb.z = (rb.z > 0.f) ? rb.z : expm1f(rb.z);
            rb.w = (rb.w > 0.f) ? rb.w : expm1f(rb.w);
        }
        *(float4*)(out + (unsigned)d * HC + cbase)     = ra;
        *(float4*)(out + (unsigned)d * HC + cbase + 4) = rb;
    }
}

// ---------------- launch ---------------------------------------------------
// 6 launches; index 3 (the ncu-profiled slot) = k_gemm1.
extern "C" void kernel_launch(void* const* d_in, const int* in_sizes, int n_in,
                              void* d_out, int out_size) {
    const float* x   = (const float*)d_in[0];
    const int*   e32 = (const int*)d_in[1];
    const float* W0  = (const float*)d_in[2];
    const float* as0 = (const float*)d_in[3];
    const float* ad0 = (const float*)d_in[4];
    const float* b0  = (const float*)d_in[5];
    const float* W1  = (const float*)d_in[6];
    const float* as1 = (const float*)d_in[7];
    const float* ad1 = (const float*)d_in[8];
    const float* b1  = (const float*)d_in[9];
    float* out = (float*)d_out;

    const int TB = 256;
    const int edge_blocks = (ET + TB - 1) / TB;
    const int node_warps  = (N_NODES + (TB / 32) - 1) / (TB / 32);

    k_fill<<<edge_blocks, TB>>>(e32);                      // 0
    k_gemm0a<<<(N_NODES + 7) / 8, 256>>>(x, W0, as0, ad0); // 1
    k_gather<0><<<node_warps, TB>>>(nullptr, b0);          // 2
    k_gemm1<<<(N_NODES + 31) / 32, 256>>>(W1);             // 3  <- profiled slot
    k_alpha1<<<node_warps, TB>>>(as1, ad1);                // 4
    k_gather<1><<<node_warps, TB>>>(out, b1);              // 5
}

// round 16
// speedup vs baseline: 1.1883x; 1.1883x over previous
#include <cuda_runtime.h>
#include <cuda_fp16.h>
#include <math.h>

// ---------------- problem constants (fixed by setup_inputs) ----------------
#define N_NODES 50000
#define N_EDGES 800000
#define ET      (N_EDGES + N_NODES)   // edges + self loops = 850000
#define H       2
#define C0      128
#define C1      100
#define F0      17
#define HC0     (H * C0)              // 256
#define HC1     (H * C1)              // 200
#define NEG_SLOPE 0.2f
#define EPS_DEN   1e-16f
#define PAD     96                    // bucket capacity; P(Poisson(17) > 96) ~ 1e-44

// ---------------- scratch (static device globals; no allocation) -----------
__device__ __align__(16) float  g_agg0[(long long)N_NODES * HC0];  // x1 after gather0
__device__ __align__(16) __half g_h0h[(long long)N_NODES * HC0];   // fp16 features L0
__device__ __align__(16) __half g_h1h[(long long)N_NODES * HC1];   // fp16 features L1
__device__ __align__(16) float  g_asrc[N_NODES * H];
__device__ __align__(16) float  g_adst[N_NODES * H];
__device__ __align__(16) int    g_pos[N_NODES];                    // degree counters
__device__ __align__(16) int    g_adjpad[(long long)N_NODES * PAD];
__device__ int g_is64;

// ---------------- helpers --------------------------------------------------
__device__ __forceinline__ int clampN(int v) {
    return v < 0 ? 0 : (v >= N_NODES ? N_NODES - 1 : v);
}
__device__ __forceinline__ float lrelu(float v) {
    return (v >= 0.0f) ? v : NEG_SLOPE * v;
}
// packed fp32x2 FMA (Blackwell; PTX-only)
__device__ __forceinline__ void fma2(unsigned long long& acc,
                                     unsigned long long a,
                                     unsigned long long b) {
    asm("fma.rn.f32x2 %0, %1, %2, %0;" : "+l"(acc) : "l"(a), "l"(b));
}
__device__ __forceinline__ unsigned long long pack2(float lo, float hi) {
    unsigned long long r;
    asm("mov.b64 %0, {%1, %2};" : "=l"(r) : "f"(lo), "f"(hi));
    return r;
}

// ---------------- init: zero bucket counters + dtype detection -------------
__global__ void k_initpos(const int* __restrict__ e32) {
    if (blockIdx.x == 0 && threadIdx.x < 32) {
        int w = e32[2 * threadIdx.x + 1];
        unsigned b = __ballot_sync(0xffffffffu, w != 0);
        if (threadIdx.x == 0) g_is64 = (b == 0) ? 1 : 0;
    }
    int i = blockIdx.x * blockDim.x + threadIdx.x;
    int stride = gridDim.x * blockDim.x;
    for (; i < N_NODES; i += stride) g_pos[i] = 0;
}

// ---------------- decode edges + self loops into padded dst buckets --------
__global__ void k_fill(const int* __restrict__ e32) {
    int i = blockIdx.x * blockDim.x + threadIdx.x;
    if (i >= ET) return;
    int s, d;
    if (i < N_EDGES) {
        if (g_is64) {
            s = e32[2 * i];
            d = e32[2 * N_EDGES + 2 * i];
        } else {
            s = e32[i];
            d = e32[N_EDGES + i];
        }
        s = clampN(s); d = clampN(d);
    } else {
        s = d = i - N_EDGES;
    }
    int slot = atomicAdd(&g_pos[d], 1);
    if (slot < PAD) g_adjpad[d * PAD + slot] = s;
}

// ---------------- GEMM layer 0 + fused alpha0 ------------------------------
__global__ void k_gemm0a(const float* __restrict__ x, const float* __restrict__ W,
                         const float* __restrict__ asrc, const float* __restrict__ adst) {
    __shared__ float xs[8][F0];
    __shared__ float sred[8][8][2];   // [warp][node][src/dst]
    const int n0 = blockIdx.x * 8;
    const int t  = threadIdx.x;  // column 0..255
    for (int i = t; i < 8 * F0; i += 256) {
        int n = i / F0, k = i % F0, nn = n0 + n;
        xs[n][k] = (nn < N_NODES) ? x[(long long)nn * F0 + k] : 0.0f;
    }
    __syncthreads();
    float acc[8];
#pragma unroll
    for (int n = 0; n < 8; n++) acc[n] = 0.0f;
#pragma unroll
    for (int k = 0; k < F0; k++) {
        float w = W[k * HC0 + t];
#pragma unroll
        for (int n = 0; n < 8; n++) acc[n] += xs[n][k] * w;
    }
#pragma unroll
    for (int n = 0; n < 8; n++) {
        int nn = n0 + n;
        if (nn < N_NODES) g_h0h[(unsigned)nn * HC0 + t] = __float2half_rn(acc[n]);
    }
    const int warp = t >> 5, lane = t & 31;
    const float as_t = asrc[t];
    const float ad_t = adst[t];
#pragma unroll
    for (int n = 0; n < 8; n++) {
        float vs = acc[n] * as_t;
        float vd = acc[n] * ad_t;
#pragma unroll
        for (int o = 16; o; o >>= 1) {
            vs += __shfl_xor_sync(0xffffffffu, vs, o);
            vd += __shfl_xor_sync(0xffffffffu, vd, o);
        }
        if (lane == 0) {
            sred[warp][n][0] = vs;
            sred[warp][n][1] = vd;
        }
    }
    __syncthreads();
    if (t < 32) {
        int n = t >> 2, hd = (t >> 1) & 1, q = t & 1;
        float s = 0.0f;
#pragma unroll
        for (int w = 0; w < 4; w++) s += sred[hd * 4 + w][n][q];
        int nn = n0 + n;
        if (nn < N_NODES) {
            if (q == 0) g_asrc[nn * H + hd] = s;
            else        g_adst[nn * H + hd] = s;
        }
    }
}

// ---------------- GEMM layer 1: register-tiled -----------------------------
// Block: 64 rows x 200 cols, k-chunk 32. Thread tile 8 rows x 8 cols (t<200):
// per k = 4 LDS.128 + 32 FFMA2 (64 FMAs) -> 4x less smem traffic per FMA.
__global__ void k_gemm1(const float* __restrict__ W) {
    __shared__ __align__(16) float xs[32][68];    // [k][row], pad for 16B rows
    __shared__ __align__(16) float ws[32][212];   // [k][col]
    const int n0 = blockIdx.x * 64;
    const int t  = threadIdx.x;
    const int rowg = t / 25;          // 0..7 row-group (rows rowg*8..+7)
    const int colg = t % 25;          // 0..24 col-group (cols colg*8..+7)
    const bool active = (t < 200);

    unsigned long long acc2[4][8];
#pragma unroll
    for (int a = 0; a < 4; a++)
#pragma unroll
        for (int b = 0; b < 8; b++) acc2[a][b] = 0ull;

    for (int kc = 0; kc < HC0; kc += 32) {
        __syncthreads();
        // stage x1 chunk: thread -> row n=t/4, k-quarter kq=t%4 (8 k each)
        {
            int n = t >> 2, kq = t & 3;
            int nn = n0 + n;
            float4 a0 = make_float4(0.f, 0.f, 0.f, 0.f), a1 = a0;
            if (nn < N_NODES) {
                const float4* src = (const float4*)&g_agg0[(unsigned)nn * HC0 + kc + kq * 8];
                a0 = src[0]; a1 = src[1];
            }
            int kb = kq * 8;
            xs[kb + 0][n] = a0.x; xs[kb + 1][n] = a0.y;
            xs[kb + 2][n] = a0.z; xs[kb + 3][n] = a0.w;
            xs[kb + 4][n] = a1.x; xs[kb + 5][n] = a1.y;
            xs[kb + 6][n] = a1.z; xs[kb + 7][n] = a1.w;
        }
        // stage W chunk (coalesced)
        for (int i = t; i < 32 * HC1; i += 256) {
            int k = i / HC1, c = i % HC1;
            ws[k][c] = W[(kc + k) * HC1 + c];
        }
        __syncthreads();
        if (active) {
#pragma unroll 4
            for (int k = 0; k < 32; k++) {
                float4 r0 = *(const float4*)&xs[k][rowg * 8];
                float4 r1 = *(const float4*)&xs[k][rowg * 8 + 4];
                float4 w0 = *(const float4*)&ws[k][colg * 8];
                float4 w1 = *(const float4*)&ws[k][colg * 8 + 4];
                unsigned long long rp0 = pack2(r0.x, r0.y);
                unsigned long long rp1 = pack2(r0.z, r0.w);
                unsigned long long rp2 = pack2(r1.x, r1.y);
                unsigned long long rp3 = pack2(r1.z, r1.w);
                float wv[8] = {w0.x, w0.y, w0.z, w0.w, w1.x, w1.y, w1.z, w1.w};
#pragma unroll
                for (int c = 0; c < 8; c++) {
                    unsigned long long w2 = pack2(wv[c], wv[c]);
                    fma2(acc2[0][c], rp0, w2);
                    fma2(acc2[1][c], rp1, w2);
                    fma2(acc2[2][c], rp2, w2);
                    fma2(acc2[3][c], rp3, w2);
                }
            }
        }
    }
    if (active) {
#pragma unroll
        for (int rp = 0; rp < 4; rp++) {
            int ra = n0 + rowg * 8 + rp * 2;
            int rb = ra + 1;
#pragma unroll
            for (int c = 0; c < 8; c++) {
                float lo, hi;
                asm("mov.b64 {%0, %1}, %2;" : "=f"(lo), "=f"(hi) : "l"(acc2[rp][c]));
                int col = colg * 8 + c;
                if (ra < N_NODES) g_h1h[(unsigned)ra * HC1 + col] = __float2half_rn(lo);
                if (rb < N_NODES) g_h1h[(unsigned)rb * HC1 + col] = __float2half_rn(hi);
            }
        }
    }
}

// ---------------- attention logits layer 1 (fp16 h, warp per node) ---------
__global__ void k_alpha1(const float* __restrict__ asrc,
                         const float* __restrict__ adst) {
    constexpr int C  = C1;
    constexpr int HC = HC1;
    constexpr int NL = HC / 8;   // 25
    const __half* h = g_h1h;

    int n    = (blockIdx.x * blockDim.x + threadIdx.x) >> 5;
    int lane = threadIdx.x & 31;
    if (n >= N_NODES) return;
    const int  cbase = 8 * lane;
    float s0 = 0.f, s1 = 0.f, d0 = 0.f, d1 = 0.f;
    if (lane < NL) {
        uint4 v = *(const uint4*)(h + (unsigned)n * HC + cbase);
        const __half2* hv = (const __half2*)&v;
        float2 f0 = __half22float2(hv[0]);
        float2 f1 = __half22float2(hv[1]);
        float2 f2 = __half22float2(hv[2]);
        float2 f3 = __half22float2(hv[3]);
        float4 aA = *(const float4*)(asrc + cbase);
        float4 aB = *(const float4*)(asrc + cbase + 4);
        float4 dA = *(const float4*)(adst + cbase);
        float4 dB = *(const float4*)(adst + cbase + 4);
        float sA = f0.x * aA.x + f0.y * aA.y + f1.x * aA.z + f1.y * aA.w;
        float sB = f2.x * aB.x + f2.y * aB.y + f3.x * aB.z + f3.y * aB.w;
        float dAv = f0.x * dA.x + f0.y * dA.y + f1.x * dA.z + f1.y * dA.w;
        float dBv = f2.x * dB.x + f2.y * dB.y + f3.x * dB.z + f3.y * dB.w;
        if (cbase >= C)     { s1 += sA; d1 += dAv; } else { s0 += sA; d0 += dAv; }
        if (cbase + 4 >= C) { s1 += sB; d1 += dBv; } else { s0 += sB; d0 += dBv; }
    }
#pragma unroll
    for (int o = 16; o; o >>= 1) {
        s0 += __shfl_xor_sync(0xffffffffu, s0, o);
        s1 += __shfl_xor_sync(0xffffffffu, s1, o);
        d0 += __shfl_xor_sync(0xffffffffu, d0, o);
        d1 += __shfl_xor_sync(0xffffffffu, d1, o);
    }
    if (lane == 0) {
        g_asrc[n * H + 0] = s0;
        g_asrc[n * H + 1] = s1;
        g_adst[n * H + 0] = d0;
        g_adst[n * H + 1] = d1;
    }
}

// ---------------- gather aggregation: one warp per dst ---------------------
template <int LAYER>
__global__ void k_gather(float* __restrict__ out_param,
                         const float* __restrict__ bias) {
    constexpr int C  = (LAYER == 0) ? C0  : C1;
    constexpr int HC = (LAYER == 0) ? HC0 : HC1;
    constexpr int NL = HC / 8;                  // load lanes: 32 (L0), 25 (L1)
    const __half* h = (LAYER == 0) ? g_h0h : g_h1h;
    float* out      = (LAYER == 0) ? g_agg0 : out_param;

    __shared__ __align__(16) float4 stage[8][32];   // [warp][edge-in-chunk]

    int d    = (blockIdx.x * blockDim.x + threadIdx.x) >> 5;
    int warp = threadIdx.x >> 5;
    int lane = threadIdx.x & 31;
    if (d >= N_NODES) return;

    const int  cbase = 8 * lane;
    const bool headA = (cbase >= C);
    const bool headB = (cbase + 4 >= C);

    const unsigned row0 = (unsigned)d * PAD;
    int deg = g_pos[d]; if (deg > PAD) deg = PAD;
    float ad0 = g_adst[d * H + 0];
    float ad1 = g_adst[d * H + 1];

    float accA0 = 0.f, accA1 = 0.f, accA2 = 0.f, accA3 = 0.f;
    float accB0 = 0.f, accB1 = 0.f, accB2 = 0.f, accB3 = 0.f;
    float s0 = 0.0f, s1 = 0.0f;
    for (int j0 = 0; j0 < deg; j0 += 32) {
        int j = j0 + lane;
        int   sn = 0;
        float p0 = 0.0f, p1 = 0.0f;
        if (j < deg) {
            sn = g_adjpad[row0 + j];
            float2 av = *(const float2*)&g_asrc[sn * H];
            p0 = __expf(fminf(lrelu(av.x + ad0), 80.0f));
            p1 = __expf(fminf(lrelu(av.y + ad1), 80.0f));
        }
        s0 += p0;
        s1 += p1;
        stage[warp][lane] = make_float4(__int_as_float(sn), p0, p1, 0.0f);
        __syncwarp();
        int cnt = deg - j0; if (cnt > 32) cnt = 32;
#pragma unroll 4
        for (int k = 0; k < cnt; k++) {
            float4 e = stage[warp][k];           // LDS.128 broadcast
            if (lane < NL) {
                unsigned sk = (unsigned)__float_as_int(e.x);
                uint4 v = *(const uint4*)(h + sk * HC + cbase);
                const __half2* hv = (const __half2*)&v;
                float2 f0 = __half22float2(hv[0]);
                float2 f1 = __half22float2(hv[1]);
                float2 f2 = __half22float2(hv[2]);
                float2 f3 = __half22float2(hv[3]);
                float wA = headA ? e.z : e.y;
                float wB = headB ? e.z : e.y;
                accA0 += wA * f0.x; accA1 += wA * f0.y;
                accA2 += wA * f1.x; accA3 += wA * f1.y;
                accB0 += wB * f2.x; accB1 += wB * f2.y;
                accB2 += wB * f3.x; accB3 += wB * f3.y;
            }
        }
        __syncwarp();
    }
#pragma unroll
    for (int o = 16; o; o >>= 1) {
        s0 += __shfl_xor_sync(0xffffffffu, s0, o);
        s1 += __shfl_xor_sync(0xffffffffu, s1, o);
    }
    float inv0 = 1.0f / (s0 + EPS_DEN);
    float inv1 = 1.0f / (s1 + EPS_DEN);

    if (lane < NL) {
        float invA = headA ? inv1 : inv0;
        float invB = headB ? inv1 : inv0;
        float4 ba = *(const float4*)(bias + cbase);
        float4 bb = *(const float4*)(bias + cbase + 4);
        float4 ra, rb;
        ra.x = accA0 * invA + ba.x; ra.y = accA1 * invA + ba.y;
        ra.z = accA2 * invA + ba.z; ra.w = accA3 * invA + ba.w;
        rb.x = accB0 * invB + bb.x; rb.y = accB1 * invB + bb.y;
        rb.z = accB2 * invB + bb.z; rb.w = accB3 * invB + bb.w;
        if (LAYER == 0) {  // ELU between layers
            ra.x = (ra.x > 0.f) ? ra.x : expm1f(ra.x);
            ra.y = (ra.y > 0.f) ? ra.y : expm1f(ra.y);
            ra.z = (ra.z > 0.f) ? ra.z : expm1f(ra.z);
            ra.w = (ra.w > 0.f) ? ra.w : expm1f(ra.w);
            rb.x = (rb.x > 0.f) ? rb.x : expm1f(rb.x);
            rb.y = (rb.y > 0.f) ? rb.y : expm1f(rb.y);
            rb.z = (rb.z > 0.f) ? rb.z : expm1f(rb.z);
            rb.w = (rb.w > 0.f) ? rb.w : expm1f(rb.w);
        }
        *(float4*)(out + (unsigned)d * HC + cbase)     = ra;
        *(float4*)(out + (unsigned)d * HC + cbase + 4) = rb;
    }
}

// ---------------- launch ---------------------------------------------------
extern "C" void kernel_launch(void* const* d_in, const int* in_sizes, int n_in,
                              void* d_out, int out_size) {
    const float* x   = (const float*)d_in[0];
    const int*   e32 = (const int*)d_in[1];
    const float* W0  = (const float*)d_in[2];
    const float* as0 = (const float*)d_in[3];
    const float* ad0 = (const float*)d_in[4];
    const float* b0  = (const float*)d_in[5];
    const float* W1  = (const float*)d_in[6];
    const float* as1 = (const float*)d_in[7];
    const float* ad1 = (const float*)d_in[8];
    const float* b1  = (const float*)d_in[9];
    float* out = (float*)d_out;

    const int TB = 256;
    const int edge_blocks = (ET + TB - 1) / TB;
    const int node_warps  = (N_NODES + (TB / 32) - 1) / (TB / 32);

    k_initpos<<<196, TB>>>(e32);                           // 0
    k_fill<<<edge_blocks, TB>>>(e32);                      // 1
    k_gemm0a<<<(N_NODES + 7) / 8, 256>>>(x, W0, as0, ad0); // 2
    k_gather<0><<<node_warps, TB>>>(nullptr, b0);          // 3  <- profiled slot
    k_gemm1<<<(N_NODES + 63) / 64, 256>>>(W1);             // 4
    k_alpha1<<<node_warps, TB>>>(as1, ad1);                // 5
    k_gather<1><<<node_warps, TB>>>(out, b1);              // 6
}